// round 1
// baseline (speedup 1.0000x reference)
#include <cuda_runtime.h>

// Problem constants
#define BATCH 2
#define SEQ   2048
#define EMB   1024
#define HEADS 16
#define HDIM  64
#define SCALE (-32.0f)

// ---------------- scratch (no cudaMalloc allowed) ----------------
__device__ float g_K[BATCH * SEQ * EMB];
__device__ float g_V[BATCH * SEQ * EMB];
__device__ float g_att[BATCH * SEQ * EMB];

// ---------------- GEMM: C[M,N] = A[M,K] @ B[N,K]^T (all row-major) ----------------
#define BM 128
#define BN 128
#define BKK 16
#define TM 8
#define TN 8
#define PADF 4

__global__ __launch_bounds__(256) void gemm_abt(const float* __restrict__ A,
                                                const float* __restrict__ B,
                                                float* __restrict__ C,
                                                int M, int N, int K)
{
    __shared__ float As[BKK][BM + PADF];
    __shared__ float Bs[BKK][BN + PADF];

    const int tid  = threadIdx.x;
    const int brow = blockIdx.y * BM;
    const int bcol = blockIdx.x * BN;
    const int tr   = (tid / (BN / TN)) * TM;   // 0..120
    const int tc   = (tid % (BN / TN)) * TN;   // 0..120

    float acc[TM][TN];
#pragma unroll
    for (int i = 0; i < TM; i++)
#pragma unroll
        for (int j = 0; j < TN; j++) acc[i][j] = 0.0f;

    for (int k0 = 0; k0 < K; k0 += BKK) {
        // cooperative load: 128 rows x 16 k per matrix = 512 float4, 2/thread
#pragma unroll
        for (int i = 0; i < 2; i++) {
            const int idx = tid + i * 256;        // 0..511
            const int m   = idx >> 2;             // 0..127
            const int kk  = (idx & 3) << 2;       // 0,4,8,12
            const float4 a = *(const float4*)(A + (size_t)(brow + m) * K + k0 + kk);
            As[kk + 0][m] = a.x; As[kk + 1][m] = a.y;
            As[kk + 2][m] = a.z; As[kk + 3][m] = a.w;
            const float4 b = *(const float4*)(B + (size_t)(bcol + m) * K + k0 + kk);
            Bs[kk + 0][m] = b.x; Bs[kk + 1][m] = b.y;
            Bs[kk + 2][m] = b.z; Bs[kk + 3][m] = b.w;
        }
        __syncthreads();

#pragma unroll
        for (int kk = 0; kk < BKK; kk++) {
            float ra[TM], rb[TN];
            *(float4*)&ra[0] = *(const float4*)&As[kk][tr];
            *(float4*)&ra[4] = *(const float4*)&As[kk][tr + 4];
            *(float4*)&rb[0] = *(const float4*)&Bs[kk][tc];
            *(float4*)&rb[4] = *(const float4*)&Bs[kk][tc + 4];
#pragma unroll
            for (int i = 0; i < TM; i++)
#pragma unroll
                for (int j = 0; j < TN; j++)
                    acc[i][j] = fmaf(ra[i], rb[j], acc[i][j]);
        }
        __syncthreads();
    }

#pragma unroll
    for (int i = 0; i < TM; i++) {
        float* cp = C + (size_t)(brow + tr + i) * N + bcol + tc;
        *(float4*)(cp)     = make_float4(acc[i][0], acc[i][1], acc[i][2], acc[i][3]);
        *(float4*)(cp + 4) = make_float4(acc[i][4], acc[i][5], acc[i][6], acc[i][7]);
    }
}

// ---------------- Flash attention (Q = K_proj, K = V = V_proj) ----------------
// logits[s,t] = SCALE * dot(K[s,:], V[t,:]); softmax over t; out = attn @ V
// One thread owns one query row entirely: q[64] + o[64] in registers,
// V tile in smem read as broadcast (all lanes same address -> conflict-free).
#define TS 16

__global__ __launch_bounds__(128) void attn_kernel(const float* __restrict__ Km,
                                                   const float* __restrict__ Vm,
                                                   float* __restrict__ Om)
{
    __shared__ float vt[TS][HDIM];

    const int tid = threadIdx.x;
    const int h   = blockIdx.y;
    const int b   = blockIdx.z;
    const int row = blockIdx.x * 128 + tid;

    const size_t head_base = (size_t)b * SEQ * EMB + (size_t)h * HDIM;
    const float* qp = Km + head_base + (size_t)row * EMB;

    float q[HDIM], o[HDIM];
#pragma unroll
    for (int i = 0; i < HDIM / 4; i++) {
        float4 t = *(const float4*)(qp + 4 * i);
        q[4 * i + 0] = t.x; q[4 * i + 1] = t.y;
        q[4 * i + 2] = t.z; q[4 * i + 3] = t.w;
    }
#pragma unroll
    for (int d = 0; d < HDIM; d++) o[d] = 0.0f;

    float m = -3.0e38f, l = 0.0f;

    for (int kt = 0; kt < SEQ; kt += TS) {
        __syncthreads();   // previous tile fully consumed
        // load TS x 64 V tile: 256 float4, 2 per thread
#pragma unroll
        for (int i = 0; i < 2; i++) {
            const int idx = tid + i * 128;       // 0..255
            const int t   = idx >> 4;            // 0..15
            const int d4  = (idx & 15) << 2;     // 0..60
            *(float4*)&vt[t][d4] =
                *(const float4*)(Vm + head_base + (size_t)(kt + t) * EMB + d4);
        }
        __syncthreads();

        float sc[TS];
#pragma unroll
        for (int t = 0; t < TS; t++) {
            float s0 = 0.f, s1 = 0.f, s2 = 0.f, s3 = 0.f;
#pragma unroll
            for (int d = 0; d < HDIM; d += 4) {
                s0 = fmaf(q[d + 0], vt[t][d + 0], s0);
                s1 = fmaf(q[d + 1], vt[t][d + 1], s1);
                s2 = fmaf(q[d + 2], vt[t][d + 2], s2);
                s3 = fmaf(q[d + 3], vt[t][d + 3], s3);
            }
            sc[t] = SCALE * ((s0 + s1) + (s2 + s3));
        }

        float tmax = sc[0];
#pragma unroll
        for (int t = 1; t < TS; t++) tmax = fmaxf(tmax, sc[t]);
        const float mn   = fmaxf(m, tmax);
        const float corr = __expf(m - mn);
        l *= corr;
#pragma unroll
        for (int d = 0; d < HDIM; d++) o[d] *= corr;

#pragma unroll
        for (int t = 0; t < TS; t++) {
            const float p = __expf(sc[t] - mn);
            l += p;
#pragma unroll
            for (int d = 0; d < HDIM; d++)
                o[d] = fmaf(p, vt[t][d], o[d]);
        }
        m = mn;
    }

    const float inv = 1.0f / l;
    float* op = Om + head_base + (size_t)row * EMB;
#pragma unroll
    for (int i = 0; i < HDIM / 4; i++) {
        float4 t;
        t.x = o[4 * i + 0] * inv; t.y = o[4 * i + 1] * inv;
        t.z = o[4 * i + 2] * inv; t.w = o[4 * i + 3] * inv;
        *(float4*)(op + 4 * i) = t;
    }
}

// ---------------- launch ----------------
extern "C" void kernel_launch(void* const* d_in, const int* in_sizes, int n_in,
                              void* d_out, int out_size)
{
    const float* x  = (const float*)d_in[0];
    // d_in[1] = Wq, unused (faithful to source)
    const float* Wk = (const float*)d_in[2];
    const float* Wv = (const float*)d_in[3];
    const float* Wo = (const float*)d_in[4];
    float* out = (float*)d_out;

    float *pK, *pV, *pA;
    cudaGetSymbolAddress((void**)&pK, g_K);
    cudaGetSymbolAddress((void**)&pV, g_V);
    cudaGetSymbolAddress((void**)&pA, g_att);

    const int M = BATCH * SEQ;   // 4096
    const int N = EMB;           // 1024
    const int K = EMB;           // 1024
    dim3 gg(N / BN, M / BM);     // (8, 32)

    gemm_abt<<<gg, 256>>>(x,  Wk, pK, M, N, K);
    gemm_abt<<<gg, 256>>>(x,  Wv, pV, M, N, K);
    attn_kernel<<<dim3(SEQ / 128, HEADS, BATCH), 128>>>(pK, pV, pA);
    gemm_abt<<<gg, 256>>>(pA, Wo, out, M, N, K);
}

// round 2
// speedup vs baseline: 5.7848x; 5.7848x over previous
#include <cuda_runtime.h>

// Problem constants
#define BATCH 2
#define SEQ   2048
#define EMB   1024
#define HEADS 16
#define HDIM  64
#define SCALE (-32.0f)

// ---------------- scratch (no cudaMalloc allowed) ----------------
__device__ float g_K[BATCH * SEQ * EMB];
__device__ float g_V[BATCH * SEQ * EMB];
__device__ float g_att[BATCH * SEQ * EMB];

// ---------------- GEMM: C[M,N] = A[M,K] @ B[N,K]^T (all row-major) ----------------
#define BM 128
#define BN 128
#define BKK 16
#define TM 8
#define TN 8
#define PADF 4

__global__ __launch_bounds__(256) void gemm_abt(const float* __restrict__ A,
                                                const float* __restrict__ B,
                                                float* __restrict__ C,
                                                int M, int N, int K)
{
    __shared__ float As[BKK][BM + PADF];
    __shared__ float Bs[BKK][BN + PADF];

    const int tid  = threadIdx.x;
    const int brow = blockIdx.y * BM;
    const int bcol = blockIdx.x * BN;
    const int tr   = (tid / (BN / TN)) * TM;
    const int tc   = (tid % (BN / TN)) * TN;

    float acc[TM][TN];
#pragma unroll
    for (int i = 0; i < TM; i++)
#pragma unroll
        for (int j = 0; j < TN; j++) acc[i][j] = 0.0f;

    for (int k0 = 0; k0 < K; k0 += BKK) {
#pragma unroll
        for (int i = 0; i < 2; i++) {
            const int idx = tid + i * 256;
            const int m   = idx >> 2;
            const int kk  = (idx & 3) << 2;
            const float4 a = *(const float4*)(A + (size_t)(brow + m) * K + k0 + kk);
            As[kk + 0][m] = a.x; As[kk + 1][m] = a.y;
            As[kk + 2][m] = a.z; As[kk + 3][m] = a.w;
            const float4 b = *(const float4*)(B + (size_t)(bcol + m) * K + k0 + kk);
            Bs[kk + 0][m] = b.x; Bs[kk + 1][m] = b.y;
            Bs[kk + 2][m] = b.z; Bs[kk + 3][m] = b.w;
        }
        __syncthreads();

#pragma unroll
        for (int kk = 0; kk < BKK; kk++) {
            float ra[TM], rb[TN];
            *(float4*)&ra[0] = *(const float4*)&As[kk][tr];
            *(float4*)&ra[4] = *(const float4*)&As[kk][tr + 4];
            *(float4*)&rb[0] = *(const float4*)&Bs[kk][tc];
            *(float4*)&rb[4] = *(const float4*)&Bs[kk][tc + 4];
#pragma unroll
            for (int i = 0; i < TM; i++)
#pragma unroll
                for (int j = 0; j < TN; j++)
                    acc[i][j] = fmaf(ra[i], rb[j], acc[i][j]);
        }
        __syncthreads();
    }

#pragma unroll
    for (int i = 0; i < TM; i++) {
        float* cp = C + (size_t)(brow + tr + i) * N + bcol + tc;
        *(float4*)(cp)     = make_float4(acc[i][0], acc[i][1], acc[i][2], acc[i][3]);
        *(float4*)(cp + 4) = make_float4(acc[i][4], acc[i][5], acc[i][6], acc[i][7]);
    }
}

// ---------------- Flash attention, tiled (Q := K_proj, K = V := V_proj) ----------------
// Per block: 64 query rows, loop over 32 key tiles of 64.
// 256 threads as 16x16; each thread owns 4x4 micro-tiles of S and O.
// XOR-swizzled smem layout (16B groups) -> conflict-free LDS.128 in both GEMMs.
// Q is pre-scaled by SCALE at load so S is directly the logits.

// swizzled index into a 64x64 float tile: row-major rows, 16B-group XOR swizzle on cols
#define SW(r, c) ((((r) << 6)) + ((((((c) >> 2) ^ ((r) >> 2)) & 15)) << 2) + ((c) & 3))

__global__ __launch_bounds__(256) void attn64(const float* __restrict__ Km,
                                              const float* __restrict__ Vm,
                                              float* __restrict__ Om)
{
    __shared__ float Qt[64 * 64];  // Qt[k][r] : Q^T, pre-scaled by SCALE
    __shared__ float Vt[64 * 64];  // Vt[k][c] : V^T for S-GEMM; reused as Pt[t][r]
    __shared__ float Vr[64 * 64];  // Vr[t][d] : V row-major for PV-GEMM

    const int tid = threadIdx.x;
    const int tx  = tid & 15;       // 0..15 -> key cols / d cols (x4)
    const int ty  = tid >> 4;       // 0..15 -> query rows (x4)
    const int b   = blockIdx.z;
    const int h   = blockIdx.y;
    const int q0  = blockIdx.x * 64;

    const size_t hb = (size_t)b * SEQ * EMB + (size_t)h * HDIM;

    // ---- load Q tile (64 rows x 64 d), transposed + scaled ----
#pragma unroll
    for (int i = 0; i < 4; i++) {
        const int idx = tid + i * 256;       // 0..1023
        const int r   = idx >> 4;            // 0..63
        const int d4  = (idx & 15) << 2;     // 0..60
        float4 v = *(const float4*)(Km + hb + (size_t)(q0 + r) * EMB + d4);
        Qt[SW(d4 + 0, r)] = v.x * SCALE;
        Qt[SW(d4 + 1, r)] = v.y * SCALE;
        Qt[SW(d4 + 2, r)] = v.z * SCALE;
        Qt[SW(d4 + 3, r)] = v.w * SCALE;
    }

    float Oacc[4][4];
    float mi[4], li[4];
#pragma unroll
    for (int i = 0; i < 4; i++) {
        mi[i] = -1.0e30f;
        li[i] = 0.0f;
#pragma unroll
        for (int j = 0; j < 4; j++) Oacc[i][j] = 0.0f;
    }

    for (int kt = 0; kt < SEQ; kt += 64) {
        __syncthreads();  // prev iteration's Pt/Vr fully consumed

        // ---- load V tile: Vt[d][t] (transposed) and Vr[t][d] ----
#pragma unroll
        for (int i = 0; i < 4; i++) {
            const int idx = tid + i * 256;
            const int t   = idx >> 4;          // 0..63 local key row
            const int d4  = (idx & 15) << 2;
            float4 v = *(const float4*)(Vm + hb + (size_t)(kt + t) * EMB + d4);
            *(float4*)&Vr[SW(t, d4)] = v;
            Vt[SW(d4 + 0, t)] = v.x;
            Vt[SW(d4 + 1, t)] = v.y;
            Vt[SW(d4 + 2, t)] = v.z;
            Vt[SW(d4 + 3, t)] = v.w;
        }
        __syncthreads();

        // ---- S = (SCALE*Q) @ V^T : 4x4 micro-tile per thread ----
        float S[4][4];
#pragma unroll
        for (int i = 0; i < 4; i++)
#pragma unroll
            for (int j = 0; j < 4; j++) S[i][j] = 0.0f;

#pragma unroll 8
        for (int k = 0; k < 64; k++) {
            float4 a = *(const float4*)&Qt[SW(k, ty << 2)];
            float4 bb = *(const float4*)&Vt[SW(k, tx << 2)];
            const float ra[4] = {a.x, a.y, a.z, a.w};
            const float rb[4] = {bb.x, bb.y, bb.z, bb.w};
#pragma unroll
            for (int i = 0; i < 4; i++)
#pragma unroll
                for (int j = 0; j < 4; j++)
                    S[i][j] = fmaf(ra[i], rb[j], S[i][j]);
        }

        __syncthreads();  // Vt reads done; safe to overwrite as Pt

        // ---- online softmax update (row stats across 16 tx lanes) ----
#pragma unroll
        for (int i = 0; i < 4; i++) {
            float rm = fmaxf(fmaxf(S[i][0], S[i][1]), fmaxf(S[i][2], S[i][3]));
#pragma unroll
            for (int msk = 1; msk < 16; msk <<= 1)
                rm = fmaxf(rm, __shfl_xor_sync(0xffffffffu, rm, msk));
            const float mn   = fmaxf(mi[i], rm);
            const float corr = __expf(mi[i] - mn);
            mi[i] = mn;

            float rs = 0.0f;
#pragma unroll
            for (int j = 0; j < 4; j++) {
                const float p = __expf(S[i][j] - mn);
                S[i][j] = p;
                rs += p;
            }
#pragma unroll
            for (int msk = 1; msk < 16; msk <<= 1)
                rs += __shfl_xor_sync(0xffffffffu, rs, msk);
            li[i] = li[i] * corr + rs;

#pragma unroll
            for (int j = 0; j < 4; j++) {
                Oacc[i][j] *= corr;
                // write P transposed: Pt[t][r], t = 4*tx+j, r = 4*ty+i
                Vt[SW((tx << 2) + j, (ty << 2) + i)] = S[i][j];
            }
        }
        __syncthreads();  // Pt visible to all

        // ---- O += P @ V : inner dim = local key t ----
#pragma unroll 8
        for (int t = 0; t < 64; t++) {
            float4 a = *(const float4*)&Vt[SW(t, ty << 2)];   // Pt[t][4ty..]
            float4 bb = *(const float4*)&Vr[SW(t, tx << 2)];  // V[t][4tx..]
            const float ra[4] = {a.x, a.y, a.z, a.w};
            const float rb[4] = {bb.x, bb.y, bb.z, bb.w};
#pragma unroll
            for (int i = 0; i < 4; i++)
#pragma unroll
                for (int j = 0; j < 4; j++)
                    Oacc[i][j] = fmaf(ra[i], rb[j], Oacc[i][j]);
        }
    }

    // ---- normalize + store ----
#pragma unroll
    for (int i = 0; i < 4; i++) {
        const float inv = 1.0f / li[i];
        float4 o;
        o.x = Oacc[i][0] * inv;
        o.y = Oacc[i][1] * inv;
        o.z = Oacc[i][2] * inv;
        o.w = Oacc[i][3] * inv;
        *(float4*)(Om + hb + (size_t)(q0 + (ty << 2) + i) * EMB + (tx << 2)) = o;
    }
}

// ---------------- launch ----------------
extern "C" void kernel_launch(void* const* d_in, const int* in_sizes, int n_in,
                              void* d_out, int out_size)
{
    const float* x  = (const float*)d_in[0];
    // d_in[1] = Wq, unused (faithful to source)
    const float* Wk = (const float*)d_in[2];
    const float* Wv = (const float*)d_in[3];
    const float* Wo = (const float*)d_in[4];
    float* out = (float*)d_out;

    float *pK, *pV, *pA;
    cudaGetSymbolAddress((void**)&pK, g_K);
    cudaGetSymbolAddress((void**)&pV, g_V);
    cudaGetSymbolAddress((void**)&pA, g_att);

    const int M = BATCH * SEQ;   // 4096
    const int N = EMB;           // 1024
    const int K = EMB;           // 1024
    dim3 gg(N / BN, M / BM);

    gemm_abt<<<gg, 256>>>(x,  Wk, pK, M, N, K);
    gemm_abt<<<gg, 256>>>(x,  Wv, pV, M, N, K);
    attn64<<<dim3(SEQ / 64, HEADS, BATCH), 256>>>(pK, pV, pA);
    gemm_abt<<<gg, 256>>>(pA, Wo, out, M, N, K);
}

// round 8
// speedup vs baseline: 14.1459x; 2.4454x over previous
#include <cuda_runtime.h>
#include <cuda_bf16.h>
#include <cstdint>

// Problem constants
#define BATCH 2
#define SEQ   2048
#define EMB   1024
#define HEADS 16
#define HDIM  64
#define SCALE (-32.0f)
#define MTOT  (BATCH * SEQ)   // 4096
#define KP    (3 * EMB)       // 3072 expanded inner dim

// ---------------- scratch (no cudaMalloc allowed) ----------------
__device__ float g_K[MTOT * EMB];
__device__ float g_V[MTOT * EMB];
__device__ float g_att[MTOT * EMB];
__device__ __nv_bfloat16 g_xE[(size_t)MTOT * KP];   // x expanded  [hi,hi,lo]
__device__ __nv_bfloat16 g_aE[(size_t)MTOT * KP];   // att expanded
__device__ __nv_bfloat16 g_WkE[(size_t)EMB * KP];   // weights expanded [hi,lo,hi]
__device__ __nv_bfloat16 g_WvE[(size_t)EMB * KP];
__device__ __nv_bfloat16 g_WoE[(size_t)EMB * KP];

// ---------------- helpers ----------------
__device__ __forceinline__ uint32_t smem_u32(const void* p) {
    uint32_t a;
    asm("{ .reg .u64 t; cvta.to.shared.u64 t, %1; cvt.u32.u64 %0, t; }" : "=r"(a) : "l"(p));
    return a;
}
#define CP_ASYNC16(dst, src) \
    asm volatile("cp.async.cg.shared.global [%0], [%1], 16;" :: "r"(dst), "l"(src))
#define CP_COMMIT()  asm volatile("cp.async.commit_group;" ::: "memory")
#define CP_WAIT(n)   asm volatile("cp.async.wait_group %0;" :: "n"(n) : "memory")

__device__ __forceinline__ void ldsm4(uint32_t* r, uint32_t addr) {
    asm volatile("ldmatrix.sync.aligned.m8n8.x4.shared.b16 {%0,%1,%2,%3}, [%4];"
                 : "=r"(r[0]), "=r"(r[1]), "=r"(r[2]), "=r"(r[3]) : "r"(addr));
}
__device__ __forceinline__ void ldsm4t(uint32_t* r, uint32_t addr) {
    asm volatile("ldmatrix.sync.aligned.m8n8.x4.trans.shared.b16 {%0,%1,%2,%3}, [%4];"
                 : "=r"(r[0]), "=r"(r[1]), "=r"(r[2]), "=r"(r[3]) : "r"(addr));
}
__device__ __forceinline__ void mma16816(float* c, const uint32_t* a, const uint32_t* b) {
    asm volatile("mma.sync.aligned.m16n8k16.row.col.f32.bf16.bf16.f32 "
                 "{%0,%1,%2,%3}, {%4,%5,%6,%7}, {%8,%9}, {%0,%1,%2,%3};"
                 : "+f"(c[0]), "+f"(c[1]), "+f"(c[2]), "+f"(c[3])
                 : "r"(a[0]), "r"(a[1]), "r"(a[2]), "r"(a[3]), "r"(b[0]), "r"(b[1]));
}
// pack two fp32 -> bf16x2 register (lo = first element, hi = second)
__device__ __forceinline__ uint32_t pack_bf16x2(float lo, float hi) {
    uint32_t r;
    asm("cvt.rn.bf16x2.f32 %0, %1, %2;" : "=r"(r) : "f"(hi), "f"(lo));
    return r;
}

// ---------------- split-bf16 expansion ----------------
// A-mode (modeA=1): dst row = [hi, hi, lo]; B-mode: [hi, lo, hi]
__global__ void expand_kernel(const float* __restrict__ src, __nv_bfloat16* __restrict__ dst,
                              int total, int modeA)
{
    for (int idx = blockIdx.x * blockDim.x + threadIdx.x; idx < total;
         idx += gridDim.x * blockDim.x) {
        const int r = idx >> 10;        // / EMB
        const int k = idx & 1023;
        const float x = src[idx];
        const __nv_bfloat16 hi = __float2bfloat16(x);
        const __nv_bfloat16 lo = __float2bfloat16(x - __bfloat162float(hi));
        const size_t b = (size_t)r * KP + k;
        dst[b] = hi;
        if (modeA) { dst[b + EMB] = hi; dst[b + 2 * EMB] = lo; }
        else       { dst[b + EMB] = lo; dst[b + 2 * EMB] = hi; }
    }
}

// ---------------- HMMA GEMM: C[M,1024] = A'[M,3072] @ B'[1024,3072]^T ----------------
#define GP 40
#define NKS (KP / 32)   // 96 k-steps of 32

__global__ __launch_bounds__(256, 2) void gemm_hmma(const __nv_bfloat16* __restrict__ A,
                                                    const __nv_bfloat16* __restrict__ B,
                                                    float* __restrict__ C)
{
    __shared__ __nv_bfloat16 sA[2][128][GP];
    __shared__ __nv_bfloat16 sB[2][128][GP];

    const int tid  = threadIdx.x;
    const int lane = tid & 31;
    const int wid  = tid >> 5;
    const int wm   = wid & 3;
    const int wn   = wid >> 2;
    const int m0   = blockIdx.y * 128;
    const int n0   = blockIdx.x * 128;

    float acc[2][8][4];
#pragma unroll
    for (int mt = 0; mt < 2; mt++)
#pragma unroll
        for (int nt = 0; nt < 8; nt++)
#pragma unroll
            for (int r = 0; r < 4; r++) acc[mt][nt][r] = 0.0f;

    const int lr0 = tid >> 2;
    const int lc  = (tid & 3) * 8;

#define LOAD_STAGE(s, ks) do {                                                   \
    const int _kc = (ks) * 32;                                                   \
    CP_ASYNC16(smem_u32(&sA[s][lr0][lc]),      A + (size_t)(m0 + lr0) * KP + _kc + lc); \
    CP_ASYNC16(smem_u32(&sA[s][lr0 + 64][lc]), A + (size_t)(m0 + lr0 + 64) * KP + _kc + lc); \
    CP_ASYNC16(smem_u32(&sB[s][lr0][lc]),      B + (size_t)(n0 + lr0) * KP + _kc + lc); \
    CP_ASYNC16(smem_u32(&sB[s][lr0 + 64][lc]), B + (size_t)(n0 + lr0 + 64) * KP + _kc + lc); \
} while (0)

    LOAD_STAGE(0, 0);
    CP_COMMIT();

    const int mi = lane >> 3;
    const int l8 = lane & 7;

    for (int ks = 0; ks < NKS; ks++) {
        const int buf = ks & 1;
        if (ks + 1 < NKS) { LOAD_STAGE(buf ^ 1, ks + 1); CP_COMMIT(); CP_WAIT(1); }
        else              { CP_WAIT(0); }
        __syncthreads();

#pragma unroll
        for (int kb = 0; kb < 32; kb += 16) {
            uint32_t af[2][4];
#pragma unroll
            for (int mt = 0; mt < 2; mt++) {
                const int row = wm * 32 + mt * 16 + (mi & 1) * 8 + l8;
                ldsm4(af[mt], smem_u32(&sA[buf][row][kb + (mi >> 1) * 8]));
            }
            uint32_t bfr[4][4];
#pragma unroll
            for (int np = 0; np < 4; np++) {
                const int row = wn * 64 + np * 16 + (mi >> 1) * 8 + l8;
                ldsm4(bfr[np], smem_u32(&sB[buf][row][kb + (mi & 1) * 8]));
            }
#pragma unroll
            for (int mt = 0; mt < 2; mt++)
#pragma unroll
                for (int nt = 0; nt < 8; nt++)
                    mma16816(acc[mt][nt], af[mt], &bfr[nt >> 1][(nt & 1) * 2]);
        }
        __syncthreads();
    }

#pragma unroll
    for (int mt = 0; mt < 2; mt++) {
        const int row = m0 + wm * 32 + mt * 16 + (lane >> 2);
#pragma unroll
        for (int nt = 0; nt < 8; nt++) {
            const int col = n0 + wn * 64 + nt * 8 + (lane & 3) * 2;
            *(float2*)&C[(size_t)row * EMB + col] = make_float2(acc[mt][nt][0], acc[mt][nt][1]);
            *(float2*)&C[(size_t)(row + 8) * EMB + col] = make_float2(acc[mt][nt][2], acc[mt][nt][3]);
        }
    }
#undef LOAD_STAGE
}

// ---------------- HMMA flash attention ----------------
// Q := K_proj (pre-scaled), K = V := V_proj. 64 q-rows/CTA, 4 warps x 16 rows.
// S  = Qhi*Vhi^T + Qhi*Vlo^T + Qlo*Vhi^T   (split-bf16, fp32 accum)
// PV = Phi*Vhi  + Phi*Vlo  + Plo*Vhi      (P in registers, split-bf16)
#define AP 72   // smem pitch (bf16): stride 144B -> conflict-free ldmatrix

__global__ __launch_bounds__(128) void attn_hmma(const float* __restrict__ Km,
                                                 const float* __restrict__ Vm,
                                                 float* __restrict__ Om)
{
    __shared__ __nv_bfloat16 sQh[64][AP];
    __shared__ __nv_bfloat16 sQl[64][AP];
    __shared__ __nv_bfloat16 sVh[64][AP];
    __shared__ __nv_bfloat16 sVl[64][AP];

    const int tid  = threadIdx.x;
    const int lane = tid & 31;
    const int w    = tid >> 5;          // 0..3, q-rows w*16..
    const int b    = blockIdx.z;
    const int h    = blockIdx.y;
    const int q0   = blockIdx.x * 64;
    const size_t hb = (size_t)b * SEQ * EMB + (size_t)h * HDIM;

    const int mi = lane >> 3;
    const int l8 = lane & 7;
    const int g  = lane >> 2;           // fragment row group
    const int tg = lane & 3;

    // ---- load Q tile (scaled by SCALE, exact: power of 2), split hi/lo ----
#pragma unroll
    for (int i = 0; i < 8; i++) {
        const int idx = tid + i * 128;       // 0..1023
        const int r   = idx >> 4;
        const int d4  = (idx & 15) << 2;
        float4 v = *(const float4*)(Km + hb + (size_t)(q0 + r) * EMB + d4);
        v.x *= SCALE; v.y *= SCALE; v.z *= SCALE; v.w *= SCALE;
        const float vv[4] = {v.x, v.y, v.z, v.w};
#pragma unroll
        for (int j = 0; j < 4; j++) {
            const __nv_bfloat16 hi = __float2bfloat16(vv[j]);
            sQh[r][d4 + j] = hi;
            sQl[r][d4 + j] = __float2bfloat16(vv[j] - __bfloat162float(hi));
        }
    }

    float O8[8][4];
#pragma unroll
    for (int nt = 0; nt < 8; nt++)
#pragma unroll
        for (int r = 0; r < 4; r++) O8[nt][r] = 0.0f;
    float mrow[2] = {-1.0e30f, -1.0e30f};
    float lrow[2] = {0.0f, 0.0f};

    for (int kt = 0; kt < SEQ; kt += 64) {
        __syncthreads();   // prev tile's V fully consumed
        // ---- load V tile, split hi/lo ----
#pragma unroll
        for (int i = 0; i < 8; i++) {
            const int idx = tid + i * 128;
            const int t   = idx >> 4;
            const int d4  = (idx & 15) << 2;
            float4 v = *(const float4*)(Vm + hb + (size_t)(kt + t) * EMB + d4);
            const float vv[4] = {v.x, v.y, v.z, v.w};
#pragma unroll
            for (int j = 0; j < 4; j++) {
                const __nv_bfloat16 hi = __float2bfloat16(vv[j]);
                sVh[t][d4 + j] = hi;
                sVl[t][d4 + j] = __float2bfloat16(vv[j] - __bfloat162float(hi));
            }
        }
        __syncthreads();

        // ---- S = Qhi*Vhi^T + Qlo*Vhi^T + Qhi*Vlo^T  (A:[q][d], B:[t][d]) ----
        float S8[8][4];
#pragma unroll
        for (int nt = 0; nt < 8; nt++)
#pragma unroll
            for (int r = 0; r < 4; r++) S8[nt][r] = 0.0f;

#pragma unroll
        for (int kb = 0; kb < 64; kb += 16) {
            uint32_t vb[4][4];
#pragma unroll
            for (int np = 0; np < 4; np++)
                ldsm4(vb[np], smem_u32(&sVh[np * 16 + (mi >> 1) * 8 + l8][kb + (mi & 1) * 8]));
            uint32_t aq[4];
            ldsm4(aq, smem_u32(&sQh[w * 16 + (mi & 1) * 8 + l8][kb + (mi >> 1) * 8]));
#pragma unroll
            for (int nt = 0; nt < 8; nt++) mma16816(S8[nt], aq, &vb[nt >> 1][(nt & 1) * 2]);
            uint32_t al[4];
            ldsm4(al, smem_u32(&sQl[w * 16 + (mi & 1) * 8 + l8][kb + (mi >> 1) * 8]));
#pragma unroll
            for (int nt = 0; nt < 8; nt++) mma16816(S8[nt], al, &vb[nt >> 1][(nt & 1) * 2]);
        }
#pragma unroll
        for (int kb = 0; kb < 64; kb += 16) {
            uint32_t vb[4][4];
#pragma unroll
            for (int np = 0; np < 4; np++)
                ldsm4(vb[np], smem_u32(&sVl[np * 16 + (mi >> 1) * 8 + l8][kb + (mi & 1) * 8]));
            uint32_t aq[4];
            ldsm4(aq, smem_u32(&sQh[w * 16 + (mi & 1) * 8 + l8][kb + (mi >> 1) * 8]));
#pragma unroll
            for (int nt = 0; nt < 8; nt++) mma16816(S8[nt], aq, &vb[nt >> 1][(nt & 1) * 2]);
        }

        // ---- online softmax on fragments (rows g and g+8) ----
        float rm0 = -1.0e30f, rm1 = -1.0e30f;
#pragma unroll
        for (int nt = 0; nt < 8; nt++) {
            rm0 = fmaxf(rm0, fmaxf(S8[nt][0], S8[nt][1]));
            rm1 = fmaxf(rm1, fmaxf(S8[nt][2], S8[nt][3]));
        }
#pragma unroll
        for (int msk = 1; msk < 4; msk <<= 1) {
            rm0 = fmaxf(rm0, __shfl_xor_sync(0xffffffffu, rm0, msk));
            rm1 = fmaxf(rm1, __shfl_xor_sync(0xffffffffu, rm1, msk));
        }
        const float mn0 = fmaxf(mrow[0], rm0);
        const float mn1 = fmaxf(mrow[1], rm1);
        const float corr0 = __expf(mrow[0] - mn0);
        const float corr1 = __expf(mrow[1] - mn1);
        mrow[0] = mn0; mrow[1] = mn1;

        uint32_t Pah[4][4], Pal[4][4];
        float rs0 = 0.0f, rs1 = 0.0f;
#pragma unroll
        for (int nt = 0; nt < 8; nt++) {
            const float p0 = __expf(S8[nt][0] - mn0);
            const float p1 = __expf(S8[nt][1] - mn0);
            const float p2 = __expf(S8[nt][2] - mn1);
            const float p3 = __expf(S8[nt][3] - mn1);
            rs0 += p0 + p1;  rs1 += p2 + p3;
            const float h0 = __bfloat162float(__float2bfloat16(p0));
            const float h1 = __bfloat162float(__float2bfloat16(p1));
            const float h2 = __bfloat162float(__float2bfloat16(p2));
            const float h3 = __bfloat162float(__float2bfloat16(p3));
            const int kc = nt >> 1, sl = (nt & 1) * 2;
            // a-frag order: {row g k0-7, row g+8 k0-7, row g k8-15, row g+8 k8-15}
            Pah[kc][sl + 0] = pack_bf16x2(h0, h1);           // rows g
            Pah[kc][sl + 1] = pack_bf16x2(h2, h3);           // rows g+8
            Pal[kc][sl + 0] = pack_bf16x2(p0 - h0, p1 - h1);
            Pal[kc][sl + 1] = pack_bf16x2(p2 - h2, p3 - h3);
        }
#pragma unroll
        for (int msk = 1; msk < 4; msk <<= 1) {
            rs0 += __shfl_xor_sync(0xffffffffu, rs0, msk);
            rs1 += __shfl_xor_sync(0xffffffffu, rs1, msk);
        }
        lrow[0] = lrow[0] * corr0 + rs0;
        lrow[1] = lrow[1] * corr1 + rs1;
#pragma unroll
        for (int nt = 0; nt < 8; nt++) {
            O8[nt][0] *= corr0; O8[nt][1] *= corr0;
            O8[nt][2] *= corr1; O8[nt][3] *= corr1;
        }

        // ---- PV: O += Phi*Vhi + Plo*Vhi + Phi*Vlo  (B via ldmatrix.trans on [t][d]) ----
        const int tr = lane & 15;           // row within 16-t chunk
        const int dc = (lane >> 4) << 3;    // 0 or 8: d sub-col
#pragma unroll
        for (int kc = 0; kc < 4; kc++) {
            uint32_t vb[4][4];
#pragma unroll
            for (int dn = 0; dn < 4; dn++)
                ldsm4t(vb[dn], smem_u32(&sVh[kc * 16 + tr][dn * 16 + dc]));
#pragma unroll
            for (int nt = 0; nt < 8; nt++) mma16816(O8[nt], Pah[kc], &vb[nt >> 1][(nt & 1) * 2]);
#pragma unroll
            for (int nt = 0; nt < 8; nt++) mma16816(O8[nt], Pal[kc], &vb[nt >> 1][(nt & 1) * 2]);
        }
#pragma unroll
        for (int kc = 0; kc < 4; kc++) {
            uint32_t vb[4][4];
#pragma unroll
            for (int dn = 0; dn < 4; dn++)
                ldsm4t(vb[dn], smem_u32(&sVl[kc * 16 + tr][dn * 16 + dc]));
#pragma unroll
            for (int nt = 0; nt < 8; nt++) mma16816(O8[nt], Pah[kc], &vb[nt >> 1][(nt & 1) * 2]);
        }
    }

    // ---- normalize + store ----
    const float inv0 = 1.0f / lrow[0];
    const float inv1 = 1.0f / lrow[1];
    const int row0 = q0 + w * 16 + g;
#pragma unroll
    for (int nt = 0; nt < 8; nt++) {
        const int col = nt * 8 + tg * 2;
        *(float2*)&Om[hb + (size_t)row0 * EMB + col] =
            make_float2(O8[nt][0] * inv0, O8[nt][1] * inv0);
        *(float2*)&Om[hb + (size_t)(row0 + 8) * EMB + col] =
            make_float2(O8[nt][2] * inv1, O8[nt][3] * inv1);
    }
}

// ---------------- launch ----------------
extern "C" void kernel_launch(void* const* d_in, const int* in_sizes, int n_in,
                              void* d_out, int out_size)
{
    const float* x  = (const float*)d_in[0];
    // d_in[1] = Wq, unused (faithful to source)
    const float* Wk = (const float*)d_in[2];
    const float* Wv = (const float*)d_in[3];
    const float* Wo = (const float*)d_in[4];
    float* out = (float*)d_out;

    float *pK, *pV, *pA;
    __nv_bfloat16 *pxE, *paE, *pWkE, *pWvE, *pWoE;
    cudaGetSymbolAddress((void**)&pK,   g_K);
    cudaGetSymbolAddress((void**)&pV,   g_V);
    cudaGetSymbolAddress((void**)&pA,   g_att);
    cudaGetSymbolAddress((void**)&pxE,  g_xE);
    cudaGetSymbolAddress((void**)&paE,  g_aE);
    cudaGetSymbolAddress((void**)&pWkE, g_WkE);
    cudaGetSymbolAddress((void**)&pWvE, g_WvE);
    cudaGetSymbolAddress((void**)&pWoE, g_WoE);

    expand_kernel<<<2048, 256>>>(x,  pxE,  MTOT * EMB, 1);
    expand_kernel<<<512,  256>>>(Wk, pWkE, EMB * EMB,  0);
    expand_kernel<<<512,  256>>>(Wv, pWvE, EMB * EMB,  0);
    expand_kernel<<<512,  256>>>(Wo, pWoE, EMB * EMB,  0);

    dim3 gg(EMB / 128, MTOT / 128);   // (8, 32)
    gemm_hmma<<<gg, 256>>>(pxE, pWkE, pK);
    gemm_hmma<<<gg, 256>>>(pxE, pWvE, pV);

    attn_hmma<<<dim3(SEQ / 64, HEADS, BATCH), 128>>>(pK, pV, pA);

    expand_kernel<<<2048, 256>>>(pA, paE, MTOT * EMB, 1);
    gemm_hmma<<<gg, 256>>>(paE, pWoE, out);
}

// round 11
// speedup vs baseline: 15.3289x; 1.0836x over previous
#include <cuda_runtime.h>
#include <cuda_bf16.h>
#include <cstdint>

// Problem constants
#define BATCH 2
#define SEQ   2048
#define EMB   1024
#define HEADS 16
#define HDIM  64
#define SCALE (-32.0f)
#define MTOT  (BATCH * SEQ)   // 4096
#define KP    (3 * EMB)       // 3072 expanded inner dim

// ---------------- scratch (no cudaMalloc allowed) ----------------
__device__ __nv_bfloat16 g_xE[(size_t)MTOT * KP];   // x expanded [hi,hi,lo]
__device__ __nv_bfloat16 g_aE[(size_t)MTOT * KP];   // attention out, expanded (written by attn epilogue)
__device__ __nv_bfloat16 g_WkE[(size_t)EMB * KP];   // weights expanded [hi,lo,hi]
__device__ __nv_bfloat16 g_WvE[(size_t)EMB * KP];
__device__ __nv_bfloat16 g_WoE[(size_t)EMB * KP];
// pre-split attention operands (bf16 hi/lo), written by gemm split-epilogue
__device__ __nv_bfloat16 g_Qh[MTOT * EMB];
__device__ __nv_bfloat16 g_Ql[MTOT * EMB];
__device__ __nv_bfloat16 g_Vh[MTOT * EMB];
__device__ __nv_bfloat16 g_Vl[MTOT * EMB];

// ---------------- helpers ----------------
__device__ __forceinline__ uint32_t smem_u32(const void* p) {
    uint32_t a;
    asm("{ .reg .u64 t; cvta.to.shared.u64 t, %1; cvt.u32.u64 %0, t; }" : "=r"(a) : "l"(p));
    return a;
}
#define CP_ASYNC16(dst, src) \
    asm volatile("cp.async.cg.shared.global [%0], [%1], 16;" :: "r"(dst), "l"(src))
#define CP_COMMIT()  asm volatile("cp.async.commit_group;" ::: "memory")
#define CP_WAIT(n)   asm volatile("cp.async.wait_group %0;" :: "n"(n) : "memory")

__device__ __forceinline__ void ldsm4(uint32_t* r, uint32_t addr) {
    asm volatile("ldmatrix.sync.aligned.m8n8.x4.shared.b16 {%0,%1,%2,%3}, [%4];"
                 : "=r"(r[0]), "=r"(r[1]), "=r"(r[2]), "=r"(r[3]) : "r"(addr));
}
__device__ __forceinline__ void ldsm4t(uint32_t* r, uint32_t addr) {
    asm volatile("ldmatrix.sync.aligned.m8n8.x4.trans.shared.b16 {%0,%1,%2,%3}, [%4];"
                 : "=r"(r[0]), "=r"(r[1]), "=r"(r[2]), "=r"(r[3]) : "r"(addr));
}
__device__ __forceinline__ void mma16816(float* c, const uint32_t* a, const uint32_t* b) {
    asm volatile("mma.sync.aligned.m16n8k16.row.col.f32.bf16.bf16.f32 "
                 "{%0,%1,%2,%3}, {%4,%5,%6,%7}, {%8,%9}, {%0,%1,%2,%3};"
                 : "+f"(c[0]), "+f"(c[1]), "+f"(c[2]), "+f"(c[3])
                 : "r"(a[0]), "r"(a[1]), "r"(a[2]), "r"(a[3]), "r"(b[0]), "r"(b[1]));
}
__device__ __forceinline__ uint32_t pack_bf16x2(float lo, float hi) {
    uint32_t r;
    asm("cvt.rn.bf16x2.f32 %0, %1, %2;" : "=r"(r) : "f"(hi), "f"(lo));
    return r;
}
// hi/lo split of one fp32 value
__device__ __forceinline__ void split1(float y, float& hf, float& lf) {
    hf = __bfloat162float(__float2bfloat16(y));
    lf = y - hf;
}

// ---------------- split-bf16 expansion (x and weights) ----------------
// A-mode (modeA=1): dst row = [hi, hi, lo]; B-mode: [hi, lo, hi]
__global__ void expand_kernel(const float* __restrict__ src, __nv_bfloat16* __restrict__ dst,
                              int total, int modeA)
{
    for (int idx = blockIdx.x * blockDim.x + threadIdx.x; idx < total;
         idx += gridDim.x * blockDim.x) {
        const int r = idx >> 10;
        const int k = idx & 1023;
        const float x = src[idx];
        const __nv_bfloat16 hi = __float2bfloat16(x);
        const __nv_bfloat16 lo = __float2bfloat16(x - __bfloat162float(hi));
        const size_t b = (size_t)r * KP + k;
        dst[b] = hi;
        if (modeA) { dst[b + EMB] = hi; dst[b + 2 * EMB] = lo; }
        else       { dst[b + EMB] = lo; dst[b + 2 * EMB] = hi; }
    }
}

// ---------------- HMMA GEMM: C[M,1024] = A'[M,3072] @ B'[1024,3072]^T ----------------
// Epilogue modes: Ch==nullptr -> fp32 C;  else -> split hi/lo bf16 pair (scaled).
#define GP 40
#define NKS (KP / 32)

__global__ __launch_bounds__(256, 2) void gemm_hmma(const __nv_bfloat16* __restrict__ A,
                                                    const __nv_bfloat16* __restrict__ B,
                                                    float* __restrict__ C,
                                                    __nv_bfloat16* __restrict__ Ch,
                                                    __nv_bfloat16* __restrict__ Cl,
                                                    float scale)
{
    __shared__ __nv_bfloat16 sA[2][128][GP];
    __shared__ __nv_bfloat16 sB[2][128][GP];

    const int tid  = threadIdx.x;
    const int lane = tid & 31;
    const int wid  = tid >> 5;
    const int wm   = wid & 3;
    const int wn   = wid >> 2;
    const int m0   = blockIdx.y * 128;
    const int n0   = blockIdx.x * 128;

    float acc[2][8][4];
#pragma unroll
    for (int mt = 0; mt < 2; mt++)
#pragma unroll
        for (int nt = 0; nt < 8; nt++)
#pragma unroll
            for (int r = 0; r < 4; r++) acc[mt][nt][r] = 0.0f;

    const int lr0 = tid >> 2;
    const int lc  = (tid & 3) * 8;

#define LOAD_STAGE(s, ks) do {                                                   \
    const int _kc = (ks) * 32;                                                   \
    CP_ASYNC16(smem_u32(&sA[s][lr0][lc]),      A + (size_t)(m0 + lr0) * KP + _kc + lc); \
    CP_ASYNC16(smem_u32(&sA[s][lr0 + 64][lc]), A + (size_t)(m0 + lr0 + 64) * KP + _kc + lc); \
    CP_ASYNC16(smem_u32(&sB[s][lr0][lc]),      B + (size_t)(n0 + lr0) * KP + _kc + lc); \
    CP_ASYNC16(smem_u32(&sB[s][lr0 + 64][lc]), B + (size_t)(n0 + lr0 + 64) * KP + _kc + lc); \
} while (0)

    LOAD_STAGE(0, 0);
    CP_COMMIT();

    const int mi = lane >> 3;
    const int l8 = lane & 7;

    for (int ks = 0; ks < NKS; ks++) {
        const int buf = ks & 1;
        if (ks + 1 < NKS) { LOAD_STAGE(buf ^ 1, ks + 1); CP_COMMIT(); CP_WAIT(1); }
        else              { CP_WAIT(0); }
        __syncthreads();

#pragma unroll
        for (int kb = 0; kb < 32; kb += 16) {
            uint32_t af[2][4];
#pragma unroll
            for (int mt = 0; mt < 2; mt++) {
                const int row = wm * 32 + mt * 16 + (mi & 1) * 8 + l8;
                ldsm4(af[mt], smem_u32(&sA[buf][row][kb + (mi >> 1) * 8]));
            }
            uint32_t bfr[4][4];
#pragma unroll
            for (int np = 0; np < 4; np++) {
                const int row = wn * 64 + np * 16 + (mi >> 1) * 8 + l8;
                ldsm4(bfr[np], smem_u32(&sB[buf][row][kb + (mi & 1) * 8]));
            }
#pragma unroll
            for (int mt = 0; mt < 2; mt++)
#pragma unroll
                for (int nt = 0; nt < 8; nt++)
                    mma16816(acc[mt][nt], af[mt], &bfr[nt >> 1][(nt & 1) * 2]);
        }
        __syncthreads();
    }

    if (Ch == nullptr) {
        // fp32 epilogue
#pragma unroll
        for (int mt = 0; mt < 2; mt++) {
            const int row = m0 + wm * 32 + mt * 16 + (lane >> 2);
#pragma unroll
            for (int nt = 0; nt < 8; nt++) {
                const int col = n0 + wn * 64 + nt * 8 + (lane & 3) * 2;
                *(float2*)&C[(size_t)row * EMB + col] = make_float2(acc[mt][nt][0], acc[mt][nt][1]);
                *(float2*)&C[(size_t)(row + 8) * EMB + col] = make_float2(acc[mt][nt][2], acc[mt][nt][3]);
            }
        }
    } else {
        // split hi/lo epilogue: y = scale*acc (fp32), hi = bf16(y), lo = bf16(y - hi)
#pragma unroll
        for (int mt = 0; mt < 2; mt++) {
            const int row = m0 + wm * 32 + mt * 16 + (lane >> 2);
#pragma unroll
            for (int nt = 0; nt < 8; nt++) {
                const int col = n0 + wn * 64 + nt * 8 + (lane & 3) * 2;
                float h0, l0, h1, l1, h2, l2, h3, l3;
                split1(acc[mt][nt][0] * scale, h0, l0);
                split1(acc[mt][nt][1] * scale, h1, l1);
                split1(acc[mt][nt][2] * scale, h2, l2);
                split1(acc[mt][nt][3] * scale, h3, l3);
                const size_t b0 = (size_t)row * EMB + col;
                const size_t b1 = (size_t)(row + 8) * EMB + col;
                *(uint32_t*)&Ch[b0] = pack_bf16x2(h0, h1);
                *(uint32_t*)&Cl[b0] = pack_bf16x2(l0, l1);
                *(uint32_t*)&Ch[b1] = pack_bf16x2(h2, h3);
                *(uint32_t*)&Cl[b1] = pack_bf16x2(l2, l3);
            }
        }
    }
#undef LOAD_STAGE
}

// ---------------- HMMA flash attention v2 + fused expand epilogue ----------------
// 128 q-rows per CTA (8 warps x 16), V tiles (64 keys) double-buffered.
// Output written directly in A-mode expanded layout [hi, hi, lo] into aE.
#define AP 72
#define ATT_SMEM 73728
#define QH_ADDR(r, c)    (sb + (r) * 144 + (c) * 2)
#define QL_ADDR(r, c)    (sb + 18432 + (r) * 144 + (c) * 2)
#define VH_ADDR(s, r, c) (sb + 36864 + (s) * 9216 + (r) * 144 + (c) * 2)
#define VL_ADDR(s, r, c) (sb + 55296 + (s) * 9216 + (r) * 144 + (c) * 2)

__global__ __launch_bounds__(256) void attn_hmma2(const __nv_bfloat16* __restrict__ Qh,
                                                  const __nv_bfloat16* __restrict__ Ql,
                                                  const __nv_bfloat16* __restrict__ Vh,
                                                  const __nv_bfloat16* __restrict__ Vl,
                                                  __nv_bfloat16* __restrict__ aE)
{
    extern __shared__ char smem[];
    const uint32_t sb = smem_u32(smem);

    const int tid  = threadIdx.x;
    const int lane = tid & 31;
    const int w    = tid >> 5;          // 0..7, q-rows w*16..
    const int b    = blockIdx.z;
    const int h    = blockIdx.y;
    const int q0   = blockIdx.x * 128;
    const size_t hb = (size_t)b * SEQ * EMB + (size_t)h * HDIM;

    const int mi = lane >> 3;
    const int l8 = lane & 7;
    const int g  = lane >> 2;
    const int tg = lane & 3;

    // ---- preload Q hi/lo (128 rows x 64) + V tile 0 ----
#pragma unroll
    for (int i = 0; i < 4; i++) {
        const int c  = tid + i * 256;        // 0..1023
        const int r  = c >> 3;
        const int k8 = (c & 7) << 3;
        CP_ASYNC16(QH_ADDR(r, k8), Qh + hb + (size_t)(q0 + r) * EMB + k8);
        CP_ASYNC16(QL_ADDR(r, k8), Ql + hb + (size_t)(q0 + r) * EMB + k8);
    }
#define LOAD_V(kt, s) do {                                                       \
    _Pragma("unroll")                                                            \
    for (int _i = 0; _i < 2; _i++) {                                             \
        const int _c  = tid + _i * 256;                                          \
        const int _t  = _c >> 3;                                                 \
        const int _k8 = (_c & 7) << 3;                                           \
        CP_ASYNC16(VH_ADDR(s, _t, _k8), Vh + hb + (size_t)((kt) + _t) * EMB + _k8); \
        CP_ASYNC16(VL_ADDR(s, _t, _k8), Vl + hb + (size_t)((kt) + _t) * EMB + _k8); \
    }                                                                            \
} while (0)
    LOAD_V(0, 0);
    CP_COMMIT();

    float O8[8][4];
#pragma unroll
    for (int nt = 0; nt < 8; nt++)
#pragma unroll
        for (int r = 0; r < 4; r++) O8[nt][r] = 0.0f;
    float mrow[2] = {-1.0e30f, -1.0e30f};
    float lrow[2] = {0.0f, 0.0f};

    const int tr = lane & 15;
    const int dc = (lane >> 4) << 3;

    for (int ti = 0; ti < SEQ / 64; ti++) {
        const int buf = ti & 1;
        if (ti + 1 < SEQ / 64) { LOAD_V((ti + 1) * 64, buf ^ 1); CP_COMMIT(); CP_WAIT(1); }
        else                   { CP_WAIT(0); }
        __syncthreads();

        // ---- S = Qhi*Vhi^T + Qlo*Vhi^T + Qhi*Vlo^T ----
        float S8[8][4];
#pragma unroll
        for (int nt = 0; nt < 8; nt++)
#pragma unroll
            for (int r = 0; r < 4; r++) S8[nt][r] = 0.0f;

#pragma unroll
        for (int kb = 0; kb < 64; kb += 16) {
            uint32_t vb[4][4];
#pragma unroll
            for (int np = 0; np < 4; np++)
                ldsm4(vb[np], VH_ADDR(buf, np * 16 + (mi >> 1) * 8 + l8, kb + (mi & 1) * 8));
            uint32_t aq[4];
            ldsm4(aq, QH_ADDR(w * 16 + (mi & 1) * 8 + l8, kb + (mi >> 1) * 8));
#pragma unroll
            for (int nt = 0; nt < 8; nt++) mma16816(S8[nt], aq, &vb[nt >> 1][(nt & 1) * 2]);
            uint32_t al[4];
            ldsm4(al, QL_ADDR(w * 16 + (mi & 1) * 8 + l8, kb + (mi >> 1) * 8));
#pragma unroll
            for (int nt = 0; nt < 8; nt++) mma16816(S8[nt], al, &vb[nt >> 1][(nt & 1) * 2]);
        }
#pragma unroll
        for (int kb = 0; kb < 64; kb += 16) {
            uint32_t vb[4][4];
#pragma unroll
            for (int np = 0; np < 4; np++)
                ldsm4(vb[np], VL_ADDR(buf, np * 16 + (mi >> 1) * 8 + l8, kb + (mi & 1) * 8));
            uint32_t aq[4];
            ldsm4(aq, QH_ADDR(w * 16 + (mi & 1) * 8 + l8, kb + (mi >> 1) * 8));
#pragma unroll
            for (int nt = 0; nt < 8; nt++) mma16816(S8[nt], aq, &vb[nt >> 1][(nt & 1) * 2]);
        }

        // ---- online softmax (rows g and g+8 of this warp's 16) ----
        float rm0 = -1.0e30f, rm1 = -1.0e30f;
#pragma unroll
        for (int nt = 0; nt < 8; nt++) {
            rm0 = fmaxf(rm0, fmaxf(S8[nt][0], S8[nt][1]));
            rm1 = fmaxf(rm1, fmaxf(S8[nt][2], S8[nt][3]));
        }
#pragma unroll
        for (int msk = 1; msk < 4; msk <<= 1) {
            rm0 = fmaxf(rm0, __shfl_xor_sync(0xffffffffu, rm0, msk));
            rm1 = fmaxf(rm1, __shfl_xor_sync(0xffffffffu, rm1, msk));
        }
        const float mn0 = fmaxf(mrow[0], rm0);
        const float mn1 = fmaxf(mrow[1], rm1);
        const float corr0 = __expf(mrow[0] - mn0);
        const float corr1 = __expf(mrow[1] - mn1);
        mrow[0] = mn0; mrow[1] = mn1;

        uint32_t Pah[4][4], Pal[4][4];
        float rs0 = 0.0f, rs1 = 0.0f;
#pragma unroll
        for (int nt = 0; nt < 8; nt++) {
            const float p0 = __expf(S8[nt][0] - mn0);
            const float p1 = __expf(S8[nt][1] - mn0);
            const float p2 = __expf(S8[nt][2] - mn1);
            const float p3 = __expf(S8[nt][3] - mn1);
            rs0 += p0 + p1;  rs1 += p2 + p3;
            const float h0 = __bfloat162float(__float2bfloat16(p0));
            const float h1 = __bfloat162float(__float2bfloat16(p1));
            const float h2 = __bfloat162float(__float2bfloat16(p2));
            const float h3 = __bfloat162float(__float2bfloat16(p3));
            const int kc = nt >> 1, sl = (nt & 1) * 2;
            Pah[kc][sl + 0] = pack_bf16x2(h0, h1);
            Pah[kc][sl + 1] = pack_bf16x2(h2, h3);
            Pal[kc][sl + 0] = pack_bf16x2(p0 - h0, p1 - h1);
            Pal[kc][sl + 1] = pack_bf16x2(p2 - h2, p3 - h3);
        }
#pragma unroll
        for (int msk = 1; msk < 4; msk <<= 1) {
            rs0 += __shfl_xor_sync(0xffffffffu, rs0, msk);
            rs1 += __shfl_xor_sync(0xffffffffu, rs1, msk);
        }
        lrow[0] = lrow[0] * corr0 + rs0;
        lrow[1] = lrow[1] * corr1 + rs1;
#pragma unroll
        for (int nt = 0; nt < 8; nt++) {
            O8[nt][0] *= corr0; O8[nt][1] *= corr0;
            O8[nt][2] *= corr1; O8[nt][3] *= corr1;
        }

        // ---- PV: O += Phi*Vhi + Plo*Vhi + Phi*Vlo ----
#pragma unroll
        for (int kc = 0; kc < 4; kc++) {
            uint32_t vb[4][4];
#pragma unroll
            for (int dn = 0; dn < 4; dn++)
                ldsm4t(vb[dn], VH_ADDR(buf, kc * 16 + tr, dn * 16 + dc));
#pragma unroll
            for (int nt = 0; nt < 8; nt++) mma16816(O8[nt], Pah[kc], &vb[nt >> 1][(nt & 1) * 2]);
#pragma unroll
            for (int nt = 0; nt < 8; nt++) mma16816(O8[nt], Pal[kc], &vb[nt >> 1][(nt & 1) * 2]);
        }
#pragma unroll
        for (int kc = 0; kc < 4; kc++) {
            uint32_t vb[4][4];
#pragma unroll
            for (int dn = 0; dn < 4; dn++)
                ldsm4t(vb[dn], VL_ADDR(buf, kc * 16 + tr, dn * 16 + dc));
#pragma unroll
            for (int nt = 0; nt < 8; nt++) mma16816(O8[nt], Pah[kc], &vb[nt >> 1][(nt & 1) * 2]);
        }
        __syncthreads();
    }

    // ---- normalize + store directly in expanded [hi,hi,lo] layout ----
    const float inv0 = 1.0f / lrow[0];
    const float inv1 = 1.0f / lrow[1];
    const int row0 = q0 + w * 16 + g;
#pragma unroll
    for (int nt = 0; nt < 8; nt++) {
        const int col = h * HDIM + nt * 8 + tg * 2;       // 0..1022, even
        const size_t base0 = (size_t)(b * SEQ + row0) * KP + col;
        const size_t base1 = (size_t)(b * SEQ + row0 + 8) * KP + col;
        float h0, l0, h1, l1, h2, l2, h3, l3;
        split1(O8[nt][0] * inv0, h0, l0);
        split1(O8[nt][1] * inv0, h1, l1);
        split1(O8[nt][2] * inv1, h2, l2);
        split1(O8[nt][3] * inv1, h3, l3);
        const uint32_t ph0 = pack_bf16x2(h0, h1);
        const uint32_t ph1 = pack_bf16x2(h2, h3);
        *(uint32_t*)&aE[base0]           = ph0;
        *(uint32_t*)&aE[base0 + EMB]     = ph0;
        *(uint32_t*)&aE[base0 + 2 * EMB] = pack_bf16x2(l0, l1);
        *(uint32_t*)&aE[base1]           = ph1;
        *(uint32_t*)&aE[base1 + EMB]     = ph1;
        *(uint32_t*)&aE[base1 + 2 * EMB] = pack_bf16x2(l2, l3);
    }
#undef LOAD_V
}

// ---------------- launch ----------------
extern "C" void kernel_launch(void* const* d_in, const int* in_sizes, int n_in,
                              void* d_out, int out_size)
{
    const float* x  = (const float*)d_in[0];
    // d_in[1] = Wq, unused (faithful to source)
    const float* Wk = (const float*)d_in[2];
    const float* Wv = (const float*)d_in[3];
    const float* Wo = (const float*)d_in[4];
    float* out = (float*)d_out;

    __nv_bfloat16 *pxE, *paE, *pWkE, *pWvE, *pWoE, *pQh, *pQl, *pVh, *pVl;
    cudaGetSymbolAddress((void**)&pxE,  g_xE);
    cudaGetSymbolAddress((void**)&paE,  g_aE);
    cudaGetSymbolAddress((void**)&pWkE, g_WkE);
    cudaGetSymbolAddress((void**)&pWvE, g_WvE);
    cudaGetSymbolAddress((void**)&pWoE, g_WoE);
    cudaGetSymbolAddress((void**)&pQh,  g_Qh);
    cudaGetSymbolAddress((void**)&pQl,  g_Ql);
    cudaGetSymbolAddress((void**)&pVh,  g_Vh);
    cudaGetSymbolAddress((void**)&pVl,  g_Vl);

    cudaFuncSetAttribute(attn_hmma2, cudaFuncAttributeMaxDynamicSharedMemorySize, ATT_SMEM);

    expand_kernel<<<2048, 256>>>(x,  pxE,  MTOT * EMB, 1);
    expand_kernel<<<512,  256>>>(Wk, pWkE, EMB * EMB,  0);
    expand_kernel<<<512,  256>>>(Wv, pWvE, EMB * EMB,  0);
    expand_kernel<<<512,  256>>>(Wo, pWoE, EMB * EMB,  0);

    dim3 gg(EMB / 128, MTOT / 128);   // (8, 32)
    // K-projection -> pre-scaled Q hi/lo ; V-projection -> V hi/lo (split epilogue)
    gemm_hmma<<<gg, 256>>>(pxE, pWkE, nullptr, pQh, pQl, SCALE);
    gemm_hmma<<<gg, 256>>>(pxE, pWvE, nullptr, pVh, pVl, 1.0f);

    attn_hmma2<<<dim3(SEQ / 128, HEADS, BATCH), 256, ATT_SMEM>>>(pQh, pQl, pVh, pVl, paE);

    // O-projection (fp32 epilogue to harness output)
    gemm_hmma<<<gg, 256>>>(paE, pWoE, out, nullptr, nullptr, 1.0f);
}

// round 13
// speedup vs baseline: 16.3551x; 1.0669x over previous
#include <cuda_runtime.h>
#include <cuda_bf16.h>
#include <cstdint>

// Problem constants
#define BATCH 2
#define SEQ   2048
#define EMB   1024
#define HEADS 16
#define HDIM  64
#define SCALE (-32.0f)
#define MTOT  (BATCH * SEQ)   // 4096
#define KP    (3 * EMB)       // 3072 expanded inner dim

// ---------------- scratch (no cudaMalloc allowed) ----------------
__device__ __nv_bfloat16 g_xE[(size_t)MTOT * KP];   // x expanded [hi,hi,lo]
__device__ __nv_bfloat16 g_aE[(size_t)MTOT * KP];   // attention out, expanded (written by attn epilogue)
__device__ __nv_bfloat16 g_WkE[(size_t)EMB * KP];   // weights expanded [hi,lo,hi]
__device__ __nv_bfloat16 g_WvE[(size_t)EMB * KP];
__device__ __nv_bfloat16 g_WoE[(size_t)EMB * KP];
// pre-split attention operands (bf16 hi/lo), written by gemm split-epilogue
__device__ __nv_bfloat16 g_Qh[MTOT * EMB];
__device__ __nv_bfloat16 g_Ql[MTOT * EMB];
__device__ __nv_bfloat16 g_Vh[MTOT * EMB];
__device__ __nv_bfloat16 g_Vl[MTOT * EMB];

// ---------------- helpers ----------------
__device__ __forceinline__ uint32_t smem_u32(const void* p) {
    uint32_t a;
    asm("{ .reg .u64 t; cvta.to.shared.u64 t, %1; cvt.u32.u64 %0, t; }" : "=r"(a) : "l"(p));
    return a;
}
#define CP_ASYNC16(dst, src) \
    asm volatile("cp.async.cg.shared.global [%0], [%1], 16;" :: "r"(dst), "l"(src))
#define CP_COMMIT()  asm volatile("cp.async.commit_group;" ::: "memory")
#define CP_WAIT(n)   asm volatile("cp.async.wait_group %0;" :: "n"(n) : "memory")

__device__ __forceinline__ void ldsm4(uint32_t* r, uint32_t addr) {
    asm volatile("ldmatrix.sync.aligned.m8n8.x4.shared.b16 {%0,%1,%2,%3}, [%4];"
                 : "=r"(r[0]), "=r"(r[1]), "=r"(r[2]), "=r"(r[3]) : "r"(addr));
}
__device__ __forceinline__ void ldsm4t(uint32_t* r, uint32_t addr) {
    asm volatile("ldmatrix.sync.aligned.m8n8.x4.trans.shared.b16 {%0,%1,%2,%3}, [%4];"
                 : "=r"(r[0]), "=r"(r[1]), "=r"(r[2]), "=r"(r[3]) : "r"(addr));
}
__device__ __forceinline__ void mma16816(float* c, const uint32_t* a, const uint32_t* b) {
    asm volatile("mma.sync.aligned.m16n8k16.row.col.f32.bf16.bf16.f32 "
                 "{%0,%1,%2,%3}, {%4,%5,%6,%7}, {%8,%9}, {%0,%1,%2,%3};"
                 : "+f"(c[0]), "+f"(c[1]), "+f"(c[2]), "+f"(c[3])
                 : "r"(a[0]), "r"(a[1]), "r"(a[2]), "r"(a[3]), "r"(b[0]), "r"(b[1]));
}
__device__ __forceinline__ uint32_t pack_bf16x2(float lo, float hi) {
    uint32_t r;
    asm("cvt.rn.bf16x2.f32 %0, %1, %2;" : "=r"(r) : "f"(hi), "f"(lo));
    return r;
}
__device__ __forceinline__ void split1(float y, float& hf, float& lf) {
    hf = __bfloat162float(__float2bfloat16(y));
    lf = y - hf;
}

// ---------------- split-bf16 expansion ----------------
// A-mode: dst row = [hi, hi, lo]
__global__ void expand_kernel(const float* __restrict__ src, __nv_bfloat16* __restrict__ dst,
                              int total, int modeA)
{
    for (int idx = blockIdx.x * blockDim.x + threadIdx.x; idx < total;
         idx += gridDim.x * blockDim.x) {
        const int r = idx >> 10;
        const int k = idx & 1023;
        const float x = src[idx];
        const __nv_bfloat16 hi = __float2bfloat16(x);
        const __nv_bfloat16 lo = __float2bfloat16(x - __bfloat162float(hi));
        const size_t b = (size_t)r * KP + k;
        dst[b] = hi;
        if (modeA) { dst[b + EMB] = hi; dst[b + 2 * EMB] = lo; }
        else       { dst[b + EMB] = lo; dst[b + 2 * EMB] = hi; }
    }
}

// fused B-mode expand of the three weight matrices in one launch
__global__ void expand3_kernel(const float* __restrict__ s0, const float* __restrict__ s1,
                               const float* __restrict__ s2,
                               __nv_bfloat16* __restrict__ d0, __nv_bfloat16* __restrict__ d1,
                               __nv_bfloat16* __restrict__ d2, int total)
{
    for (int idx = blockIdx.x * blockDim.x + threadIdx.x; idx < total;
         idx += gridDim.x * blockDim.x) {
        const int r = idx >> 10;
        const int k = idx & 1023;
        const size_t b = (size_t)r * KP + k;
        {
            const float x = s0[idx];
            const __nv_bfloat16 hi = __float2bfloat16(x);
            d0[b] = hi; d0[b + EMB] = __float2bfloat16(x - __bfloat162float(hi)); d0[b + 2 * EMB] = hi;
        }
        {
            const float x = s1[idx];
            const __nv_bfloat16 hi = __float2bfloat16(x);
            d1[b] = hi; d1[b + EMB] = __float2bfloat16(x - __bfloat162float(hi)); d1[b + 2 * EMB] = hi;
        }
        {
            const float x = s2[idx];
            const __nv_bfloat16 hi = __float2bfloat16(x);
            d2[b] = hi; d2[b + EMB] = __float2bfloat16(x - __bfloat162float(hi)); d2[b + 2 * EMB] = hi;
        }
    }
}

// ---------------- HMMA GEMM: C[M,1024] = A'[M,3072] @ B'[1024,3072]^T ----------------
// 3-stage cp.async ring in dynamic smem; one __syncthreads per K-step.
// Epilogue modes: Ch==nullptr -> fp32 C;  else -> split hi/lo bf16 pair (scaled).
#define GP 40
#define NKS (KP / 32)            // 96 k-steps of 32
#define G_STAGE 20480            // A(10240) + B(10240) per stage
#define G_SMEM  (3 * G_STAGE)    // 61440
#define SA_ADDR(s, r, c) (sbg + (s) * G_STAGE + (r) * (GP * 2) + (c) * 2)
#define SB_ADDR(s, r, c) (sbg + (s) * G_STAGE + 10240 + (r) * (GP * 2) + (c) * 2)

__global__ __launch_bounds__(256, 2) void gemm_hmma(const __nv_bfloat16* __restrict__ A,
                                                    const __nv_bfloat16* __restrict__ B,
                                                    float* __restrict__ C,
                                                    __nv_bfloat16* __restrict__ Ch,
                                                    __nv_bfloat16* __restrict__ Cl,
                                                    float scale)
{
    extern __shared__ char gsm[];
    const uint32_t sbg = smem_u32(gsm);

    const int tid  = threadIdx.x;
    const int lane = tid & 31;
    const int wid  = tid >> 5;
    const int wm   = wid & 3;
    const int wn   = wid >> 2;
    const int m0   = blockIdx.y * 128;
    const int n0   = blockIdx.x * 128;

    float acc[2][8][4];
#pragma unroll
    for (int mt = 0; mt < 2; mt++)
#pragma unroll
        for (int nt = 0; nt < 8; nt++)
#pragma unroll
            for (int r = 0; r < 4; r++) acc[mt][nt][r] = 0.0f;

    const int lr0 = tid >> 2;
    const int lc  = (tid & 3) * 8;

#define LOAD_STAGE(s, ks) do {                                                   \
    const int _kc = (ks) * 32;                                                   \
    CP_ASYNC16(SA_ADDR(s, lr0, lc),      A + (size_t)(m0 + lr0) * KP + _kc + lc); \
    CP_ASYNC16(SA_ADDR(s, lr0 + 64, lc), A + (size_t)(m0 + lr0 + 64) * KP + _kc + lc); \
    CP_ASYNC16(SB_ADDR(s, lr0, lc),      B + (size_t)(n0 + lr0) * KP + _kc + lc); \
    CP_ASYNC16(SB_ADDR(s, lr0 + 64, lc), B + (size_t)(n0 + lr0 + 64) * KP + _kc + lc); \
} while (0)

    LOAD_STAGE(0, 0);
    CP_COMMIT();
    LOAD_STAGE(1, 1);
    CP_COMMIT();

    const int mi = lane >> 3;
    const int l8 = lane & 7;

    for (int ks = 0; ks < NKS; ks++) {
        const int buf = ks % 3;
        // stage ks must be complete; newest group (ks+1, if issued) may still fly
        if (ks + 1 < NKS) { CP_WAIT(1); } else { CP_WAIT(0); }
        __syncthreads();   // all warps done with stage (ks-1)%3's compute; buffer (ks+2)%3 free
        if (ks + 2 < NKS) { LOAD_STAGE((ks + 2) % 3, ks + 2); CP_COMMIT(); }

#pragma unroll
        for (int kb = 0; kb < 32; kb += 16) {
            uint32_t af[2][4];
#pragma unroll
            for (int mt = 0; mt < 2; mt++) {
                const int row = wm * 32 + mt * 16 + (mi & 1) * 8 + l8;
                ldsm4(af[mt], SA_ADDR(buf, row, kb + (mi >> 1) * 8));
            }
            uint32_t bfr[4][4];
#pragma unroll
            for (int np = 0; np < 4; np++) {
                const int row = wn * 64 + np * 16 + (mi >> 1) * 8 + l8;
                ldsm4(bfr[np], SB_ADDR(buf, row, kb + (mi & 1) * 8));
            }
#pragma unroll
            for (int mt = 0; mt < 2; mt++)
#pragma unroll
                for (int nt = 0; nt < 8; nt++)
                    mma16816(acc[mt][nt], af[mt], &bfr[nt >> 1][(nt & 1) * 2]);
        }
    }

    if (Ch == nullptr) {
#pragma unroll
        for (int mt = 0; mt < 2; mt++) {
            const int row = m0 + wm * 32 + mt * 16 + (lane >> 2);
#pragma unroll
            for (int nt = 0; nt < 8; nt++) {
                const int col = n0 + wn * 64 + nt * 8 + (lane & 3) * 2;
                *(float2*)&C[(size_t)row * EMB + col] = make_float2(acc[mt][nt][0], acc[mt][nt][1]);
                *(float2*)&C[(size_t)(row + 8) * EMB + col] = make_float2(acc[mt][nt][2], acc[mt][nt][3]);
            }
        }
    } else {
#pragma unroll
        for (int mt = 0; mt < 2; mt++) {
            const int row = m0 + wm * 32 + mt * 16 + (lane >> 2);
#pragma unroll
            for (int nt = 0; nt < 8; nt++) {
                const int col = n0 + wn * 64 + nt * 8 + (lane & 3) * 2;
                float h0, l0, h1, l1, h2, l2, h3, l3;
                split1(acc[mt][nt][0] * scale, h0, l0);
                split1(acc[mt][nt][1] * scale, h1, l1);
                split1(acc[mt][nt][2] * scale, h2, l2);
                split1(acc[mt][nt][3] * scale, h3, l3);
                const size_t b0 = (size_t)row * EMB + col;
                const size_t b1 = (size_t)(row + 8) * EMB + col;
                *(uint32_t*)&Ch[b0] = pack_bf16x2(h0, h1);
                *(uint32_t*)&Cl[b0] = pack_bf16x2(l0, l1);
                *(uint32_t*)&Ch[b1] = pack_bf16x2(h2, h3);
                *(uint32_t*)&Cl[b1] = pack_bf16x2(l2, l3);
            }
        }
    }
#undef LOAD_STAGE
}

// ---------------- HMMA flash attention (unchanged, proven) ----------------
#define AP 72
#define ATT_SMEM 73728
#define QH_ADDR(r, c)    (sb + (r) * 144 + (c) * 2)
#define QL_ADDR(r, c)    (sb + 18432 + (r) * 144 + (c) * 2)
#define VH_ADDR(s, r, c) (sb + 36864 + (s) * 9216 + (r) * 144 + (c) * 2)
#define VL_ADDR(s, r, c) (sb + 55296 + (s) * 9216 + (r) * 144 + (c) * 2)

__global__ __launch_bounds__(256) void attn_hmma2(const __nv_bfloat16* __restrict__ Qh,
                                                  const __nv_bfloat16* __restrict__ Ql,
                                                  const __nv_bfloat16* __restrict__ Vh,
                                                  const __nv_bfloat16* __restrict__ Vl,
                                                  __nv_bfloat16* __restrict__ aE)
{
    extern __shared__ char smem[];
    const uint32_t sb = smem_u32(smem);

    const int tid  = threadIdx.x;
    const int lane = tid & 31;
    const int w    = tid >> 5;
    const int b    = blockIdx.z;
    const int h    = blockIdx.y;
    const int q0   = blockIdx.x * 128;
    const size_t hb = (size_t)b * SEQ * EMB + (size_t)h * HDIM;

    const int mi = lane >> 3;
    const int l8 = lane & 7;
    const int g  = lane >> 2;
    const int tg = lane & 3;

#pragma unroll
    for (int i = 0; i < 4; i++) {
        const int c  = tid + i * 256;
        const int r  = c >> 3;
        const int k8 = (c & 7) << 3;
        CP_ASYNC16(QH_ADDR(r, k8), Qh + hb + (size_t)(q0 + r) * EMB + k8);
        CP_ASYNC16(QL_ADDR(r, k8), Ql + hb + (size_t)(q0 + r) * EMB + k8);
    }
#define LOAD_V(kt, s) do {                                                       \
    _Pragma("unroll")                                                            \
    for (int _i = 0; _i < 2; _i++) {                                             \
        const int _c  = tid + _i * 256;                                          \
        const int _t  = _c >> 3;                                                 \
        const int _k8 = (_c & 7) << 3;                                           \
        CP_ASYNC16(VH_ADDR(s, _t, _k8), Vh + hb + (size_t)((kt) + _t) * EMB + _k8); \
        CP_ASYNC16(VL_ADDR(s, _t, _k8), Vl + hb + (size_t)((kt) + _t) * EMB + _k8); \
    }                                                                            \
} while (0)
    LOAD_V(0, 0);
    CP_COMMIT();

    float O8[8][4];
#pragma unroll
    for (int nt = 0; nt < 8; nt++)
#pragma unroll
        for (int r = 0; r < 4; r++) O8[nt][r] = 0.0f;
    float mrow[2] = {-1.0e30f, -1.0e30f};
    float lrow[2] = {0.0f, 0.0f};

    const int tr = lane & 15;
    const int dc = (lane >> 4) << 3;

    for (int ti = 0; ti < SEQ / 64; ti++) {
        const int buf = ti & 1;
        if (ti + 1 < SEQ / 64) { LOAD_V((ti + 1) * 64, buf ^ 1); CP_COMMIT(); CP_WAIT(1); }
        else                   { CP_WAIT(0); }
        __syncthreads();

        float S8[8][4];
#pragma unroll
        for (int nt = 0; nt < 8; nt++)
#pragma unroll
            for (int r = 0; r < 4; r++) S8[nt][r] = 0.0f;

#pragma unroll
        for (int kb = 0; kb < 64; kb += 16) {
            uint32_t vb[4][4];
#pragma unroll
            for (int np = 0; np < 4; np++)
                ldsm4(vb[np], VH_ADDR(buf, np * 16 + (mi >> 1) * 8 + l8, kb + (mi & 1) * 8));
            uint32_t aq[4];
            ldsm4(aq, QH_ADDR(w * 16 + (mi & 1) * 8 + l8, kb + (mi >> 1) * 8));
#pragma unroll
            for (int nt = 0; nt < 8; nt++) mma16816(S8[nt], aq, &vb[nt >> 1][(nt & 1) * 2]);
            uint32_t al[4];
            ldsm4(al, QL_ADDR(w * 16 + (mi & 1) * 8 + l8, kb + (mi >> 1) * 8));
#pragma unroll
            for (int nt = 0; nt < 8; nt++) mma16816(S8[nt], al, &vb[nt >> 1][(nt & 1) * 2]);
        }
#pragma unroll
        for (int kb = 0; kb < 64; kb += 16) {
            uint32_t vb[4][4];
#pragma unroll
            for (int np = 0; np < 4; np++)
                ldsm4(vb[np], VL_ADDR(buf, np * 16 + (mi >> 1) * 8 + l8, kb + (mi & 1) * 8));
            uint32_t aq[4];
            ldsm4(aq, QH_ADDR(w * 16 + (mi & 1) * 8 + l8, kb + (mi >> 1) * 8));
#pragma unroll
            for (int nt = 0; nt < 8; nt++) mma16816(S8[nt], aq, &vb[nt >> 1][(nt & 1) * 2]);
        }

        float rm0 = -1.0e30f, rm1 = -1.0e30f;
#pragma unroll
        for (int nt = 0; nt < 8; nt++) {
            rm0 = fmaxf(rm0, fmaxf(S8[nt][0], S8[nt][1]));
            rm1 = fmaxf(rm1, fmaxf(S8[nt][2], S8[nt][3]));
        }
#pragma unroll
        for (int msk = 1; msk < 4; msk <<= 1) {
            rm0 = fmaxf(rm0, __shfl_xor_sync(0xffffffffu, rm0, msk));
            rm1 = fmaxf(rm1, __shfl_xor_sync(0xffffffffu, rm1, msk));
        }
        const float mn0 = fmaxf(mrow[0], rm0);
        const float mn1 = fmaxf(mrow[1], rm1);
        const float corr0 = __expf(mrow[0] - mn0);
        const float corr1 = __expf(mrow[1] - mn1);
        mrow[0] = mn0; mrow[1] = mn1;

        uint32_t Pah[4][4], Pal[4][4];
        float rs0 = 0.0f, rs1 = 0.0f;
#pragma unroll
        for (int nt = 0; nt < 8; nt++) {
            const float p0 = __expf(S8[nt][0] - mn0);
            const float p1 = __expf(S8[nt][1] - mn0);
            const float p2 = __expf(S8[nt][2] - mn1);
            const float p3 = __expf(S8[nt][3] - mn1);
            rs0 += p0 + p1;  rs1 += p2 + p3;
            const float h0 = __bfloat162float(__float2bfloat16(p0));
            const float h1 = __bfloat162float(__float2bfloat16(p1));
            const float h2 = __bfloat162float(__float2bfloat16(p2));
            const float h3 = __bfloat162float(__float2bfloat16(p3));
            const int kc = nt >> 1, sl = (nt & 1) * 2;
            Pah[kc][sl + 0] = pack_bf16x2(h0, h1);
            Pah[kc][sl + 1] = pack_bf16x2(h2, h3);
            Pal[kc][sl + 0] = pack_bf16x2(p0 - h0, p1 - h1);
            Pal[kc][sl + 1] = pack_bf16x2(p2 - h2, p3 - h3);
        }
#pragma unroll
        for (int msk = 1; msk < 4; msk <<= 1) {
            rs0 += __shfl_xor_sync(0xffffffffu, rs0, msk);
            rs1 += __shfl_xor_sync(0xffffffffu, rs1, msk);
        }
        lrow[0] = lrow[0] * corr0 + rs0;
        lrow[1] = lrow[1] * corr1 + rs1;
#pragma unroll
        for (int nt = 0; nt < 8; nt++) {
            O8[nt][0] *= corr0; O8[nt][1] *= corr0;
            O8[nt][2] *= corr1; O8[nt][3] *= corr1;
        }

#pragma unroll
        for (int kc = 0; kc < 4; kc++) {
            uint32_t vb[4][4];
#pragma unroll
            for (int dn = 0; dn < 4; dn++)
                ldsm4t(vb[dn], VH_ADDR(buf, kc * 16 + tr, dn * 16 + dc));
#pragma unroll
            for (int nt = 0; nt < 8; nt++) mma16816(O8[nt], Pah[kc], &vb[nt >> 1][(nt & 1) * 2]);
#pragma unroll
            for (int nt = 0; nt < 8; nt++) mma16816(O8[nt], Pal[kc], &vb[nt >> 1][(nt & 1) * 2]);
        }
#pragma unroll
        for (int kc = 0; kc < 4; kc++) {
            uint32_t vb[4][4];
#pragma unroll
            for (int dn = 0; dn < 4; dn++)
                ldsm4t(vb[dn], VL_ADDR(buf, kc * 16 + tr, dn * 16 + dc));
#pragma unroll
            for (int nt = 0; nt < 8; nt++) mma16816(O8[nt], Pah[kc], &vb[nt >> 1][(nt & 1) * 2]);
        }
        __syncthreads();
    }

    // ---- normalize + store directly in expanded [hi,hi,lo] layout ----
    const float inv0 = 1.0f / lrow[0];
    const float inv1 = 1.0f / lrow[1];
    const int row0 = q0 + w * 16 + g;
#pragma unroll
    for (int nt = 0; nt < 8; nt++) {
        const int col = h * HDIM + nt * 8 + tg * 2;
        const size_t base0 = (size_t)(b * SEQ + row0) * KP + col;
        const size_t base1 = (size_t)(b * SEQ + row0 + 8) * KP + col;
        float h0, l0, h1, l1, h2, l2, h3, l3;
        split1(O8[nt][0] * inv0, h0, l0);
        split1(O8[nt][1] * inv0, h1, l1);
        split1(O8[nt][2] * inv1, h2, l2);
        split1(O8[nt][3] * inv1, h3, l3);
        const uint32_t ph0 = pack_bf16x2(h0, h1);
        const uint32_t ph1 = pack_bf16x2(h2, h3);
        *(uint32_t*)&aE[base0]           = ph0;
        *(uint32_t*)&aE[base0 + EMB]     = ph0;
        *(uint32_t*)&aE[base0 + 2 * EMB] = pack_bf16x2(l0, l1);
        *(uint32_t*)&aE[base1]           = ph1;
        *(uint32_t*)&aE[base1 + EMB]     = ph1;
        *(uint32_t*)&aE[base1 + 2 * EMB] = pack_bf16x2(l2, l3);
    }
#undef LOAD_V
}

// ---------------- launch ----------------
extern "C" void kernel_launch(void* const* d_in, const int* in_sizes, int n_in,
                              void* d_out, int out_size)
{
    const float* x  = (const float*)d_in[0];
    // d_in[1] = Wq, unused (faithful to source)
    const float* Wk = (const float*)d_in[2];
    const float* Wv = (const float*)d_in[3];
    const float* Wo = (const float*)d_in[4];
    float* out = (float*)d_out;

    __nv_bfloat16 *pxE, *paE, *pWkE, *pWvE, *pWoE, *pQh, *pQl, *pVh, *pVl;
    cudaGetSymbolAddress((void**)&pxE,  g_xE);
    cudaGetSymbolAddress((void**)&paE,  g_aE);
    cudaGetSymbolAddress((void**)&pWkE, g_WkE);
    cudaGetSymbolAddress((void**)&pWvE, g_WvE);
    cudaGetSymbolAddress((void**)&pWoE, g_WoE);
    cudaGetSymbolAddress((void**)&pQh,  g_Qh);
    cudaGetSymbolAddress((void**)&pQl,  g_Ql);
    cudaGetSymbolAddress((void**)&pVh,  g_Vh);
    cudaGetSymbolAddress((void**)&pVl,  g_Vl);

    cudaFuncSetAttribute(attn_hmma2, cudaFuncAttributeMaxDynamicSharedMemorySize, ATT_SMEM);
    cudaFuncSetAttribute(gemm_hmma,  cudaFuncAttributeMaxDynamicSharedMemorySize, G_SMEM);

    expand_kernel<<<2048, 256>>>(x, pxE, MTOT * EMB, 1);
    expand3_kernel<<<1024, 256>>>(Wk, Wv, Wo, pWkE, pWvE, pWoE, EMB * EMB);

    dim3 gg(EMB / 128, MTOT / 128);   // (8, 32)
    gemm_hmma<<<gg, 256, G_SMEM>>>(pxE, pWkE, nullptr, pQh, pQl, SCALE);
    gemm_hmma<<<gg, 256, G_SMEM>>>(pxE, pWvE, nullptr, pVh, pVl, 1.0f);

    attn_hmma2<<<dim3(SEQ / 128, HEADS, BATCH), 256, ATT_SMEM>>>(pQh, pQl, pVh, pVl, paE);

    gemm_hmma<<<gg, 256, G_SMEM>>>(paE, pWoE, out, nullptr, nullptr, 1.0f);
}